// round 6
// baseline (speedup 1.0000x reference)
#include <cuda_runtime.h>
#include <math.h>

// RoIPool (max) — features (2,256,50,76) f32, rois (128,5) f32 -> out (128,256,7,7) f32
// Bin arithmetic matches the XLA-lowered JAX reference bit-for-bit (x/7 lowered to
// x * fp32(1/7)).
// R6 structure:
//  - per-block (=per-roi) bin bounds precomputed once into smem (49x redundancy removed)
//  - uniform per-roi tier dispatch -> templated NHxNW predicated gather (no divergence)
//  - 2 channels per thread (c, c+128): shared bin bounds, 2x ILP in the gather.

#define C_     256
#define H_     50
#define W_     76
#define HW_    (H_ * W_)
#define PH_    7
#define PW_    7
#define NROIS_ 128
#define SCALE_ 0.0625f
// fp32 nearest to 1/7 (0x3E124925)
#define RECIP7_ 0.14285714924335479736328125f

#define TPB_   224              // 7 warps; 28 blocks x 224 = 6272 = 12544/2 outputs
#define BPR_   28

template<int NH, int NW>
__device__ __forceinline__ void pool2(const float* __restrict__ p0,
                                      const float* __restrict__ p1,
                                      int nh, int nw,
                                      float& m0, float& m1)
{
    #pragma unroll
    for (int i = 0; i < NH; ++i) {
        #pragma unroll
        for (int j = 0; j < NW; ++j) {
            if (i < nh && j < nw) {
                m0 = fmaxf(m0, __ldg(p0 + i * W_ + j));
                m1 = fmaxf(m1, __ldg(p1 + i * W_ + j));
            }
        }
    }
}

__global__ void roipool_kernel(const float* __restrict__ feat,
                               const float* __restrict__ rois,
                               float* __restrict__ out)
{
    const int roi = blockIdx.y;
    const int tid = threadIdx.x;

    __shared__ int2 sh[PH_];     // {hstart, hend}
    __shared__ int2 sw[PW_];     // {wstart, wend}
    __shared__ int  sbase;       // batch plane offset
    __shared__ int  sth, stw;    // tier codes

    // ---- per-roi precompute (14 threads) ----
    if (tid < 14) {
        const float* r = rois + roi * 5;
        if (tid < PH_) {
            const int y1 = (int)rintf(__fmul_rn(r[2], SCALE_));
            const int y2 = (int)rintf(__fmul_rn(r[4], SCALE_));
            const float bh = __fmul_rn((float)max(y2 - y1 + 1, 1), RECIP7_);
            int hs = (int)floorf(__fmul_rn((float)tid,       bh)) + y1;
            int he = (int)ceilf (__fmul_rn((float)(tid + 1), bh)) + y1;
            hs = min(max(hs, 0), H_);
            he = min(max(he, 0), H_);
            sh[tid] = make_int2(hs, he);
            if (tid == 0) {
                sth   = (bh <= 1.0f) ? 2 : (bh <= 2.0f) ? 3 : (bh <= 3.0f) ? 4 : 0;
                sbase = (int)r[0] * (C_ * HW_);
            }
        } else {
            const int p  = tid - PH_;
            const int x1 = (int)rintf(__fmul_rn(r[1], SCALE_));
            const int x2 = (int)rintf(__fmul_rn(r[3], SCALE_));
            const float bw = __fmul_rn((float)max(x2 - x1 + 1, 1), RECIP7_);
            int ws = (int)floorf(__fmul_rn((float)p,       bw)) + x1;
            int we = (int)ceilf (__fmul_rn((float)(p + 1), bw)) + x1;
            ws = min(max(ws, 0), W_);
            we = min(max(we, 0), W_);
            sw[p] = make_int2(ws, we);
            if (p == 0)
                stw = (bw <= 1.0f) ? 2 : (bw <= 2.0f) ? 3 : (bw <= 3.0f) ? 4 : 0;
        }
    }
    __syncthreads();

    // ---- per-thread: 2 outputs (channels c and c+128, same bin) ----
    const int t  = blockIdx.x * TPB_ + tid;        // 0 .. 6271
    const int c  = t / (PH_ * PW_);                // 0 .. 127
    const int s  = t - c * (PH_ * PW_);
    const int ph = s / PW_;
    const int pw = s - ph * PW_;

    const int2 hb = sh[ph];
    const int2 wb = sw[pw];
    const int  nh = hb.y - hb.x;
    const int  nw = wb.y - wb.x;

    const float* p0 = feat + sbase + c * HW_ + hb.x * W_ + wb.x;
    const float* p1 = p0 + 128 * HW_;

    const int th = sth, tw = stw;                  // uniform per block

    float m0 = -3.402823466e+38f, m1 = -3.402823466e+38f;

    if (th && tw) {
        if (th == 2) {
            if      (tw == 2) pool2<2,2>(p0, p1, nh, nw, m0, m1);
            else if (tw == 3) pool2<2,3>(p0, p1, nh, nw, m0, m1);
            else              pool2<2,4>(p0, p1, nh, nw, m0, m1);
        } else if (th == 3) {
            if      (tw == 2) pool2<3,2>(p0, p1, nh, nw, m0, m1);
            else if (tw == 3) pool2<3,3>(p0, p1, nh, nw, m0, m1);
            else              pool2<3,4>(p0, p1, nh, nw, m0, m1);
        } else {
            if      (tw == 2) pool2<4,2>(p0, p1, nh, nw, m0, m1);
            else if (tw == 3) pool2<4,3>(p0, p1, nh, nw, m0, m1);
            else              pool2<4,4>(p0, p1, nh, nw, m0, m1);
        }
    } else {
        // Seed-robust generic fallback (bin_sz > 3 not expected with this dist).
        for (int i = 0; i < nh; ++i)
            for (int j = 0; j < nw; ++j) {
                m0 = fmaxf(m0, __ldg(p0 + i * W_ + j));
                m1 = fmaxf(m1, __ldg(p1 + i * W_ + j));
            }
    }

    if (nh <= 0 || nw <= 0) { m0 = 0.0f; m1 = 0.0f; }   // empty bin -> 0

    const size_t o0 = (size_t)roi * (C_ * PH_ * PW_) + (size_t)c * (PH_ * PW_) + s;
    out[o0]                       = m0;
    out[o0 + 128 * (PH_ * PW_)]   = m1;
}

extern "C" void kernel_launch(void* const* d_in, const int* in_sizes, int n_in,
                              void* d_out, int out_size)
{
    // Autodetect input order by element count (rois = 640 elems, features = 1,945,600).
    const float* feat;
    const float* rois;
    if (in_sizes[0] == NROIS_ * 5) {
        rois = (const float*)d_in[0];
        feat = (const float*)d_in[1];
    } else {
        feat = (const float*)d_in[0];
        rois = (const float*)d_in[1];
    }
    float* out = (float*)d_out;

    dim3 block(TPB_);
    dim3 grid(BPR_, NROIS_);     // 28 x 128 blocks, 2 outputs/thread, exact coverage
    roipool_kernel<<<grid, block>>>(feat, rois, out);
}